// round 16
// baseline (speedup 1.0000x reference)
#include <cuda_runtime.h>
#include <cuda_fp16.h>
#include <cstdint>

#define BATCH 65536
#define NG 512
#define MT 32            // batch rows per CTA
#define LDA 296          // sH leading dim (halves): conflict-free LDSM
#define LDC 132          // c leading dim (floats): conflict-free epilogue
#define NT 256           // 8 warps per CTA, 2 CTAs/SM
#define SLABH 16384      // halves per fragment-ordered slab (512 gate-cols x 32 K)
#define SLABU 2048       // uint4 per slab

// ---- fragment-ordered weight slabs in gmem, in CONSUMPTION order ----
// enc block: [L0 ks0..4 | L1 ks4..7 | L1 ks0..3] = pos 0..12; dec block: pos 13..25
// layer0 slab 4 (pos 4 / pos 17) is consumed as a HALF slab (kf0 only, K 128..143).
// slab layout: [wn 0..7][chunk 0..7][lane 0..31] of uint4 -> per-thread mma B frags
__device__ __align__(16) __half g_S[26 * SLABH];
__device__ float g_bias[4 * NG];

// ---- smem map (bytes, per CTA) ----
#define SMO_H    0          // 32 x 296 fp16 (18944)
#define SMO_C0   18944      // 32 x 132 fp32 (16896)
#define SMO_C1   35840      // 32 x 132 fp32 (16896)
#define SMO_BIAS 52736      // 4 x 512 fp32 (8192)
#define SMO_OW   60928      // 256 fp32 (1024)
#define SMO_OB   61952      // 2 fp32
#define SMEM_TOTAL 61960

// ---------------- helpers ----------------
__device__ __forceinline__ unsigned smem_u32(const void* p) {
    return (unsigned)__cvta_generic_to_shared(p);
}
__device__ __forceinline__ unsigned tanh2u(unsigned x) {
    unsigned y; asm("tanh.approx.f16x2 %0, %1;" : "=r"(y) : "r"(x)); return y;
}
__device__ __forceinline__ unsigned pack2(float a, float b) {
    __half2 h = __floats2half2_rn(a, b);
    return *reinterpret_cast<unsigned*>(&h);
}
__device__ __forceinline__ __half2 u2h(unsigned u) {
    return *reinterpret_cast<__half2*>(&u);
}
__device__ __forceinline__ void ldsm4(unsigned addr, unsigned& r0, unsigned& r1,
                                      unsigned& r2, unsigned& r3) {
    asm volatile("ldmatrix.sync.aligned.m8n8.x4.shared.b16 {%0,%1,%2,%3}, [%4];"
                 : "=r"(r0), "=r"(r1), "=r"(r2), "=r"(r3) : "r"(addr));
}
__device__ __forceinline__ void mma16816(float* d, const unsigned* a, unsigned b0, unsigned b1) {
    asm volatile(
        "mma.sync.aligned.m16n8k16.row.col.f32.f16.f16.f32 "
        "{%0,%1,%2,%3},{%4,%5,%6,%7},{%8,%9},{%0,%1,%2,%3};"
        : "+f"(d[0]), "+f"(d[1]), "+f"(d[2]), "+f"(d[3])
        : "r"(a[0]), "r"(a[1]), "r"(a[2]), "r"(a[3]), "r"(b0), "r"(b1));
}

// ---------------- prep: gate-interleave + K-fold + prescale + FRAGMENT layout ----------
// permuted gate-col np = wn*64 + q*16 + gg*8 + tg*2 + e; g = gg*2+e (i,f,g,o);
// h = wn*16 + q*4 + tg. Fragment: thread (wn, lane), chunk c = kf*4 + nip, half hh:
//   fi = hh>>2 (ni = nip*2+fi); breg = (hh&3)>>1; kp = hh&1;
//   k = kf*16 + breg*8 + (lane&3)*2 + kp;  np = wn*64 + ni*8 + (lane>>2)
__global__ void build_weights(
    const float* __restrict__ eWih0, const float* __restrict__ eWhh0,
    const float* __restrict__ ebih0, const float* __restrict__ ebhh0,
    const float* __restrict__ eWih1, const float* __restrict__ eWhh1,
    const float* __restrict__ ebih1, const float* __restrict__ ebhh1,
    const float* __restrict__ dWih0, const float* __restrict__ dWhh0,
    const float* __restrict__ dbih0, const float* __restrict__ dbhh0,
    const float* __restrict__ dWih1, const float* __restrict__ dWhh1,
    const float* __restrict__ dbih1, const float* __restrict__ dbhh1)
{
    int sb = blockIdx.x;        // 0..25
    int phase, ks;
    if (sb < 5)       { phase = 0; ks = sb; }
    else if (sb < 13) { phase = 1; ks = sb - 5; }
    else if (sb < 18) { phase = 2; ks = sb - 13; }
    else              { phase = 3; ks = sb - 18; }

    int pos;
    if (phase == 0)      pos = ks;
    else if (phase == 1) pos = (ks >= 4) ? 5 + (ks - 4) : 9 + ks;
    else if (phase == 2) pos = 13 + ks;
    else                 pos = (ks >= 4) ? 18 + (ks - 4) : 22 + ks;
    __half* dst = g_S + (size_t)pos * SLABH;

    int tid = threadIdx.x;          // 0..255
    int wn = tid >> 5, lane = tid & 31;

    for (int c = 0; c < 8; c++) {
        int kf = c >> 2, nip = c & 3;
        for (int hh = 0; hh < 8; hh++) {
            int fi = hh >> 2;
            int ni = nip * 2 + fi;
            int breg = (hh & 3) >> 1;
            int kp = hh & 1;
            int k = kf * 16 + breg * 8 + (lane & 3) * 2 + kp;
            int np = wn * 64 + ni * 8 + (lane >> 2);
            int r = np & 63;
            int q = r >> 4;
            int r2 = r & 15;
            int gg = r2 >> 3;
            int tg = (r2 & 7) >> 1;
            int e = r2 & 1;
            int g = gg * 2 + e;
            int h = wn * 16 + q * 4 + tg;
            int src = g * 128 + h;
            float scale = (g == 2) ? 1.0f : 0.5f;

            int kglob = ks * 32 + k;
            float v = 0.0f;
            if (phase == 0) {
                if (kglob < 128) v = eWhh0[src * 128 + kglob];
                else if (kglob < 135) v = eWih0[src * 7 + (kglob - 128)];
            } else if (phase == 1) {
                v = (kglob < 128) ? eWih1[src * 128 + kglob] : eWhh1[src * 128 + kglob - 128];
            } else if (phase == 2) {
                if (kglob < 128) v = dWhh0[src * 128 + kglob];
                else if (kglob < 130) v = dWih0[src * 2 + (kglob - 128)];
            } else {
                v = (kglob < 128) ? dWih1[src * 128 + kglob] : dWhh1[src * 128 + kglob - 128];
            }
            dst[(wn * 256 + c * 32 + lane) * 8 + hh] = __float2half(v * scale);
        }
    }
    if (ks == 0) {
        for (int np = tid; np < NG; np += 256) {
            int wnn = np >> 6;
            int r = np & 63;
            int q = r >> 4;
            int r2 = r & 15;
            int gg = r2 >> 3;
            int tg = (r2 & 7) >> 1;
            int e = r2 & 1;
            int g = gg * 2 + e;
            int h = wnn * 16 + q * 4 + tg;
            int src = g * 128 + h;
            float scale = (g == 2) ? 1.0f : 0.5f;
            const float* bi = (phase == 0) ? ebih0 : (phase == 1) ? ebih1 : (phase == 2) ? dbih0 : dbih1;
            const float* bh = (phase == 0) ? ebhh0 : (phase == 1) ? ebhh1 : (phase == 2) ? dbhh0 : dbhh1;
            g_bias[phase * NG + np] = (bi[src] + bh[src]) * scale;
        }
    }
}

// ---------------- acc init with bias (acc[mi 0..1][ni 0..7][4]) ----------------
__device__ __forceinline__ void init_acc(float (&acc)[2][8][4], const float* bias,
                                         int lane, int wn)
{
#pragma unroll
    for (int ni = 0; ni < 8; ni++) {
        int c0 = wn * 64 + ni * 8 + 2 * (lane & 3);
        float b0 = bias[c0], b1 = bias[c0 + 1];
#pragma unroll
        for (int mi = 0; mi < 2; mi++) {
            acc[mi][ni][0] = b0; acc[mi][ni][1] = b1;
            acc[mi][ni][2] = b0; acc[mi][ni][3] = b1;
        }
    }
}

// ---------------- NSL full slabs: kf-split software-pipelined B LDGs ----------------
// R0 carries kf0 fragments of the NEXT slab (cross-phase: caller keeps it alive).
template <int NSL, int ACOL0>
__device__ __forceinline__ void mma_slabs(
    float (&acc)[2][8][4], uint4 (&R0)[4], int lane, int wn, __half* sH,
    const __half* Wbase, const __half* Wnext)
{
    const uint4* base = (const uint4*)Wbase + wn * 256 + lane;
    const uint4* nbase = (const uint4*)Wnext + wn * 256 + lane;
#pragma unroll
    for (int j = 0; j < NSL; j++) {
        const int acol = ACOL0 + j * 32;

        uint4 R1[4];
#pragma unroll
        for (int c = 0; c < 4; c++) R1[c] = __ldg(base + j * SLABU + (4 + c) * 32);

        {   // MMA kf0 (uses R0, pre-loaded)
            unsigned a[2][4];
#pragma unroll
            for (int mi = 0; mi < 2; mi++) {
                unsigned addr = smem_u32(sH + (mi * 16 + (lane & 15)) * LDA
                                            + acol + (lane >> 4) * 8);
                ldsm4(addr, a[mi][0], a[mi][1], a[mi][2], a[mi][3]);
            }
#pragma unroll
            for (int nq = 0; nq < 4; nq++) {
                const uint4& cA = R0[nq];
#pragma unroll
                for (int mi = 0; mi < 2; mi++) {
                    mma16816(acc[mi][2 * nq],     a[mi], cA.x, cA.y);
                    mma16816(acc[mi][2 * nq + 1], a[mi], cA.z, cA.w);
                }
            }
        }

        const uint4* nxt = (j + 1 < NSL) ? base + (j + 1) * SLABU : nbase;
#pragma unroll
        for (int c = 0; c < 4; c++) R0[c] = __ldg(nxt + c * 32);

        {   // MMA kf1 (uses R1)
            unsigned a[2][4];
#pragma unroll
            for (int mi = 0; mi < 2; mi++) {
                unsigned addr = smem_u32(sH + (mi * 16 + (lane & 15)) * LDA
                                            + acol + 16 + (lane >> 4) * 8);
                ldsm4(addr, a[mi][0], a[mi][1], a[mi][2], a[mi][3]);
            }
#pragma unroll
            for (int nq = 0; nq < 4; nq++) {
                const uint4& cB = R1[nq];
#pragma unroll
                for (int mi = 0; mi < 2; mi++) {
                    mma16816(acc[mi][2 * nq],     a[mi], cB.x, cB.y);
                    mma16816(acc[mi][2 * nq + 1], a[mi], cB.z, cB.w);
                }
            }
        }
    }
}

// ---------------- half slab: consumes R0 (kf0 of the half slab, K 128..143) ----------
// Preloads kf0 of the next phase's first slab into R0.
__device__ __forceinline__ void mma_halfslab(
    float (&acc)[2][8][4], uint4 (&R0)[4], int lane, int wn, __half* sH,
    const __half* Wnext)
{
    const uint4* nbase = (const uint4*)Wnext + wn * 256 + lane;
    uint4 Rn[4];
#pragma unroll
    for (int c = 0; c < 4; c++) Rn[c] = __ldg(nbase + c * 32);

    unsigned a[2][4];
#pragma unroll
    for (int mi = 0; mi < 2; mi++) {
        unsigned addr = smem_u32(sH + (mi * 16 + (lane & 15)) * LDA
                                    + 128 + (lane >> 4) * 8);
        ldsm4(addr, a[mi][0], a[mi][1], a[mi][2], a[mi][3]);
    }
#pragma unroll
    for (int nq = 0; nq < 4; nq++) {
        const uint4& cA = R0[nq];
#pragma unroll
        for (int mi = 0; mi < 2; mi++) {
            mma16816(acc[mi][2 * nq],     a[mi], cA.x, cA.y);
            mma16816(acc[mi][2 * nq + 1], a[mi], cA.z, cA.w);
        }
    }
#pragma unroll
    for (int c = 0; c < 4; c++) R0[c] = Rn[c];
}

// ---------------- shuffle-free epilogue: compute / store ----------------
__device__ __forceinline__ void epi_compute(
    float (&acc)[2][8][4], int lane, int wn, float* sC, unsigned (&hh)[8])
{
    const int t = lane & 3, a = lane >> 2;
    const __half2 h05 = __floats2half2_rn(0.5f, 0.5f);
#pragma unroll
    for (int mi = 0; mi < 2; mi++) {
        int r0 = mi * 16 + a;
#pragma unroll
        for (int q = 0; q < 4; q++) {
            float* dA = acc[mi][2 * q];
            float* dB = acc[mi][2 * q + 1];
            __half2 si = __hfma2(u2h(tanh2u(pack2(dA[0], dA[2]))), h05, h05);
            __half2 sf = __hfma2(u2h(tanh2u(pack2(dA[1], dA[3]))), h05, h05);
            __half2 tg = u2h(tanh2u(pack2(dB[0], dB[2])));
            __half2 so = __hfma2(u2h(tanh2u(pack2(dB[1], dB[3]))), h05, h05);
            int hidx = wn * 16 + q * 4 + t;
            float2 fsi = __half22float2(si);
            float2 fsf = __half22float2(sf);
            float2 ftg = __half22float2(tg);
            float c0 = fsf.x * sC[r0 * LDC + hidx] + fsi.x * ftg.x;
            float c1 = fsf.y * sC[(r0 + 8) * LDC + hidx] + fsi.y * ftg.y;
            sC[r0 * LDC + hidx] = c0;
            sC[(r0 + 8) * LDC + hidx] = c1;
            __half2 hv = __hmul2(u2h(tanh2u(pack2(c0, c1))), so);
            hh[mi * 4 + q] = *reinterpret_cast<unsigned*>(&hv);
        }
    }
}
__device__ __forceinline__ void epi_store(
    const unsigned (&hh)[8], int lane, int wn, __half* sH, int hOff)
{
    const int t = lane & 3, a = lane >> 2;
#pragma unroll
    for (int mi = 0; mi < 2; mi++) {
        int r0 = mi * 16 + a;
#pragma unroll
        for (int q = 0; q < 4; q++) {
            __half2 hv = u2h(hh[mi * 4 + q]);
            int hidx = wn * 16 + q * 4 + t;
            sH[r0 * LDA + hOff + hidx]       = __low2half(hv);
            sH[(r0 + 8) * LDA + hOff + hidx] = __high2half(hv);
        }
    }
}

// ---------------- projection: pred = h1 @ outW^T + outb (8 warps x 4 rows) ----------
__device__ __forceinline__ void projection(
    int t, int warp, int lane, long m0, __half* sH,
    const float* sOW, const float* sOB, float* __restrict__ dout)
{
#pragma unroll
    for (int r4 = 0; r4 < 4; r4++) {
        int mloc = warp * 4 + r4;
        float a0 = 0.0f, a1 = 0.0f;
#pragma unroll
        for (int j = 0; j < 4; j++) {
            int k = lane + 32 * j;
            float hv = __half2float(sH[mloc * LDA + 160 + k]);
            a0 += hv * sOW[k];
            a1 += hv * sOW[128 + k];
        }
#pragma unroll
        for (int off = 16; off > 0; off >>= 1) {
            a0 += __shfl_down_sync(0xffffffffu, a0, off);
            a1 += __shfl_down_sync(0xffffffffu, a1, off);
        }
        if (lane == 0) {
            a0 += sOB[0];
            a1 += sOB[1];
            long m = m0 + mloc;
            dout[m * 50 + t * 2 + 0] = a0;
            dout[m * 50 + t * 2 + 1] = a1;
            sH[mloc * LDA + 128] = __float2half(a0);
            sH[mloc * LDA + 129] = __float2half(a1);
        }
    }
}

// ---------------- the fused full-network kernel (2 CTAs/SM) ----------------
__global__ __launch_bounds__(NT, 2)
void lstm_fused(const float* __restrict__ target,
                const float* __restrict__ outW, const float* __restrict__ outb,
                float* __restrict__ dout)
{
    extern __shared__ char smem[];
    __half* sH    = (__half*)(smem + SMO_H);
    float*  sC0   = (float*)(smem + SMO_C0);
    float*  sC1   = (float*)(smem + SMO_C1);
    float*  sBias = (float*)(smem + SMO_BIAS);
    float*  sOW   = (float*)(smem + SMO_OW);
    float*  sOB   = (float*)(smem + SMO_OB);

    int tid  = threadIdx.x;
    int warp = tid >> 5, lane = tid & 31;
    long m0 = (long)blockIdx.x * MT;

    // ---- init ----
    for (int i = tid; i < MT * LDA; i += NT) sH[i] = __float2half(0.0f);
    for (int i = tid; i < MT * LDC; i += NT) { sC0[i] = 0.0f; sC1[i] = 0.0f; }
    for (int i = tid; i < 4 * NG; i += NT) sBias[i] = g_bias[i];
    if (tid < 256) sOW[tid] = outW[tid];
    if (tid < 2) sOB[tid] = outb[tid];
    for (int i = tid; i < MT * 7; i += NT) {    // stage x(0)
        int m = i / 7, k = i - m * 7;
        sH[m * LDA + 128 + k] = __float2half(target[(m0 + m) * 140 + k]);
    }
    __syncthreads();

    float acc[2][8][4];
    unsigned hh[8];
    uint4 R0[4];
    {   // prologue: preload phase-0 slab-0 kf0 fragments
        const uint4* p0 = (const uint4*)g_S + warp * 256 + lane;
#pragma unroll
        for (int c = 0; c < 4; c++) R0[c] = __ldg(p0 + c * 32);
    }

    // ---- encoder: 20 steps ----
    for (int t = 0; t < 20; t++) {
        // P1: layer0 (4 full slabs @0..127 + half slab @128..143) + epi0 compute
        init_acc(acc, sBias, lane, warp);
        mma_slabs<4, 0>(acc, R0, lane, warp, sH, g_S, g_S + 4 * SLABH);
        mma_halfslab(acc, R0, lane, warp, sH, g_S + 5 * SLABH);
        epi_compute(acc, lane, warp, sC0, hh);
        __syncthreads();
        // P2: epi0 store (h0 @0..127) + layer1 h1-slabs (read 160..287)
        epi_store(hh, lane, warp, sH, 0);
        init_acc(acc, sBias + NG, lane, warp);
        mma_slabs<4, 160>(acc, R0, lane, warp, sH, g_S + 5 * SLABH, g_S + 9 * SLABH);
        __syncthreads();
        // P3: layer1 h0-slabs (read 0..127) + epi1 (write 160..287) + stage-x
        mma_slabs<4, 0>(acc, R0, lane, warp, sH, g_S + 9 * SLABH,
                        (t < 19) ? g_S : g_S + 13 * SLABH);
        epi_compute(acc, lane, warp, sC1, hh);
        epi_store(hh, lane, warp, sH, 160);
        if (t < 19) {
            for (int i = tid; i < MT * 7; i += NT) {
                int m = i / 7, k = i - m * 7;
                sH[m * LDA + 128 + k] = __float2half(target[(m0 + m) * 140 + (t + 1) * 7 + k]);
            }
        }
        __syncthreads();
    }

    // zero pred input for first decoder step (cols 130..143 hit zero weights)
    for (int i = tid; i < MT * 2; i += NT) {
        int m = i >> 1, k = i & 1;
        sH[m * LDA + 128 + k] = __float2half(0.0f);
    }
    __syncthreads();

    // ---- decoder: 25 steps (projection of step t-1 overlapped into step t) ----
    for (int t = 0; t < 25; t++) {
        // A: layer0 slabs 0..3 (read h0 @0..127) + projection(t-1) (read 160..287, write 128..129)
        init_acc(acc, sBias + 2 * NG, lane, warp);
        mma_slabs<4, 0>(acc, R0, lane, warp, sH, g_S + 13 * SLABH, g_S + 17 * SLABH);
        if (t > 0) projection(t - 1, warp, lane, m0, sH, sOW, sOB, dout);
        __syncthreads();   // pred visible; all 0..127 reads + proj reads done
        // B: half slab (read 128..143) + epi0 compute + store (write 0..127, disjoint)
        mma_halfslab(acc, R0, lane, warp, sH, g_S + 18 * SLABH);
        epi_compute(acc, lane, warp, sC0, hh);
        epi_store(hh, lane, warp, sH, 0);
        // C: layer1 h1-slabs (read old h1 @160..287 — untouched in B)
        init_acc(acc, sBias + 3 * NG, lane, warp);
        mma_slabs<4, 160>(acc, R0, lane, warp, sH, g_S + 18 * SLABH, g_S + 22 * SLABH);
        __syncthreads();   // h0 stores visible; all 160..287 reads done
        // D: layer1 h0-slabs (read new h0 @0..127) + epi1 (write 160..287)
        mma_slabs<4, 0>(acc, R0, lane, warp, sH, g_S + 22 * SLABH, g_S + 13 * SLABH);
        epi_compute(acc, lane, warp, sC1, hh);
        epi_store(hh, lane, warp, sH, 160);
        __syncthreads();   // h1 visible for next iteration's projection
    }
    projection(24, warp, lane, m0, sH, sOW, sOB, dout);
}

// ---------------- host ----------------
extern "C" void kernel_launch(void* const* d_in, const int* in_sizes, int n_in,
                              void* d_out, int out_size)
{
    const float* target = (const float*)d_in[0];
    const float* eWih0 = (const float*)d_in[4];
    const float* eWhh0 = (const float*)d_in[5];
    const float* ebih0 = (const float*)d_in[6];
    const float* ebhh0 = (const float*)d_in[7];
    const float* eWih1 = (const float*)d_in[8];
    const float* eWhh1 = (const float*)d_in[9];
    const float* ebih1 = (const float*)d_in[10];
    const float* ebhh1 = (const float*)d_in[11];
    const float* dWih0 = (const float*)d_in[12];
    const float* dWhh0 = (const float*)d_in[13];
    const float* dbih0 = (const float*)d_in[14];
    const float* dbhh0 = (const float*)d_in[15];
    const float* dWih1 = (const float*)d_in[16];
    const float* dWhh1 = (const float*)d_in[17];
    const float* dbih1 = (const float*)d_in[18];
    const float* dbhh1 = (const float*)d_in[19];
    const float* outW  = (const float*)d_in[20];
    const float* outb  = (const float*)d_in[21];
    float* out = (float*)d_out;

    cudaFuncSetAttribute(lstm_fused, cudaFuncAttributeMaxDynamicSharedMemorySize, SMEM_TOTAL);

    build_weights<<<26, 256>>>(eWih0, eWhh0, ebih0, ebhh0,
                               eWih1, eWhh1, ebih1, ebhh1,
                               dWih0, dWhh0, dbih0, dbhh0,
                               dWih1, dWhh1, dbih1, dbhh1);

    lstm_fused<<<BATCH / MT, NT, SMEM_TOTAL>>>(target, outW, outb, out);
}

// round 17
// speedup vs baseline: 1.0501x; 1.0501x over previous
#include <cuda_runtime.h>
#include <cuda_fp16.h>
#include <cstdint>

#define BATCH 65536
#define NG 512
#define MT 32            // batch rows per CTA
#define LDA 296          // sH leading dim (halves): conflict-free LDSM
#define LDC 132          // c leading dim (floats): conflict-free epilogue
#define NT 256           // 8 warps per CTA, 2 CTAs/SM
#define SLABH 16384      // halves per fragment-ordered slab (512 gate-cols x 32 K)
#define SLABU 2048       // uint4 per slab

// ---- fragment-ordered weight slabs in gmem, in CONSUMPTION order ----
// enc block: [L0 ks0..4 | L1 ks4..7 | L1 ks0..3] = pos 0..12; dec block: pos 13..25
// layer0 slab 4 (pos 4 / pos 17) is consumed as a HALF slab (kf0 only, K 128..143).
// slab layout: [wn 0..7][chunk 0..7][lane 0..31] of uint4 -> per-thread mma B frags
__device__ __align__(16) __half g_S[26 * SLABH];
__device__ float g_bias[4 * NG];

// ---- smem map (bytes, per CTA) ----
#define SMO_H    0          // 32 x 296 fp16 (18944)
#define SMO_C0   18944      // 32 x 132 fp32 (16896)
#define SMO_C1   35840      // 32 x 132 fp32 (16896)
#define SMO_BIAS 52736      // 4 x 512 fp32 (8192)
#define SMO_OW   60928      // 256 fp32 (1024)
#define SMO_OB   61952      // 2 fp32
#define SMEM_TOTAL 61960

// ---------------- helpers ----------------
__device__ __forceinline__ unsigned smem_u32(const void* p) {
    return (unsigned)__cvta_generic_to_shared(p);
}
__device__ __forceinline__ unsigned tanh2u(unsigned x) {
    unsigned y; asm("tanh.approx.f16x2 %0, %1;" : "=r"(y) : "r"(x)); return y;
}
__device__ __forceinline__ unsigned pack2(float a, float b) {
    __half2 h = __floats2half2_rn(a, b);
    return *reinterpret_cast<unsigned*>(&h);
}
__device__ __forceinline__ __half2 u2h(unsigned u) {
    return *reinterpret_cast<__half2*>(&u);
}
__device__ __forceinline__ void ldsm4(unsigned addr, unsigned& r0, unsigned& r1,
                                      unsigned& r2, unsigned& r3) {
    asm volatile("ldmatrix.sync.aligned.m8n8.x4.shared.b16 {%0,%1,%2,%3}, [%4];"
                 : "=r"(r0), "=r"(r1), "=r"(r2), "=r"(r3) : "r"(addr));
}
__device__ __forceinline__ void mma16816(float* d, const unsigned* a, unsigned b0, unsigned b1) {
    asm volatile(
        "mma.sync.aligned.m16n8k16.row.col.f32.f16.f16.f32 "
        "{%0,%1,%2,%3},{%4,%5,%6,%7},{%8,%9},{%0,%1,%2,%3};"
        : "+f"(d[0]), "+f"(d[1]), "+f"(d[2]), "+f"(d[3])
        : "r"(a[0]), "r"(a[1]), "r"(a[2]), "r"(a[3]), "r"(b0), "r"(b1));
}

// ---------------- prep: gate-interleave + K-fold + prescale + FRAGMENT layout ----------
// permuted gate-col np = wn*64 + q*16 + gg*8 + tg*2 + e; g = gg*2+e (i,f,g,o);
// h = wn*16 + q*4 + tg. Fragment: thread (wn, lane), chunk c = kf*4 + nip, half hh:
//   fi = hh>>2 (ni = nip*2+fi); breg = (hh&3)>>1; kp = hh&1;
//   k = kf*16 + breg*8 + (lane&3)*2 + kp;  np = wn*64 + ni*8 + (lane>>2)
__global__ void build_weights(
    const float* __restrict__ eWih0, const float* __restrict__ eWhh0,
    const float* __restrict__ ebih0, const float* __restrict__ ebhh0,
    const float* __restrict__ eWih1, const float* __restrict__ eWhh1,
    const float* __restrict__ ebih1, const float* __restrict__ ebhh1,
    const float* __restrict__ dWih0, const float* __restrict__ dWhh0,
    const float* __restrict__ dbih0, const float* __restrict__ dbhh0,
    const float* __restrict__ dWih1, const float* __restrict__ dWhh1,
    const float* __restrict__ dbih1, const float* __restrict__ dbhh1)
{
    int sb = blockIdx.x;        // 0..25
    int phase, ks;
    if (sb < 5)       { phase = 0; ks = sb; }
    else if (sb < 13) { phase = 1; ks = sb - 5; }
    else if (sb < 18) { phase = 2; ks = sb - 13; }
    else              { phase = 3; ks = sb - 18; }

    int pos;
    if (phase == 0)      pos = ks;
    else if (phase == 1) pos = (ks >= 4) ? 5 + (ks - 4) : 9 + ks;
    else if (phase == 2) pos = 13 + ks;
    else                 pos = (ks >= 4) ? 18 + (ks - 4) : 22 + ks;
    __half* dst = g_S + (size_t)pos * SLABH;

    int tid = threadIdx.x;          // 0..255
    int wn = tid >> 5, lane = tid & 31;

    for (int c = 0; c < 8; c++) {
        int kf = c >> 2, nip = c & 3;
        for (int hh = 0; hh < 8; hh++) {
            int fi = hh >> 2;
            int ni = nip * 2 + fi;
            int breg = (hh & 3) >> 1;
            int kp = hh & 1;
            int k = kf * 16 + breg * 8 + (lane & 3) * 2 + kp;
            int np = wn * 64 + ni * 8 + (lane >> 2);
            int r = np & 63;
            int q = r >> 4;
            int r2 = r & 15;
            int gg = r2 >> 3;
            int tg = (r2 & 7) >> 1;
            int e = r2 & 1;
            int g = gg * 2 + e;
            int h = wn * 16 + q * 4 + tg;
            int src = g * 128 + h;
            float scale = (g == 2) ? 1.0f : 0.5f;

            int kglob = ks * 32 + k;
            float v = 0.0f;
            if (phase == 0) {
                if (kglob < 128) v = eWhh0[src * 128 + kglob];
                else if (kglob < 135) v = eWih0[src * 7 + (kglob - 128)];
            } else if (phase == 1) {
                v = (kglob < 128) ? eWih1[src * 128 + kglob] : eWhh1[src * 128 + kglob - 128];
            } else if (phase == 2) {
                if (kglob < 128) v = dWhh0[src * 128 + kglob];
                else if (kglob < 130) v = dWih0[src * 2 + (kglob - 128)];
            } else {
                v = (kglob < 128) ? dWih1[src * 128 + kglob] : dWhh1[src * 128 + kglob - 128];
            }
            dst[(wn * 256 + c * 32 + lane) * 8 + hh] = __float2half(v * scale);
        }
    }
    if (ks == 0) {
        for (int np = tid; np < NG; np += 256) {
            int wnn = np >> 6;
            int r = np & 63;
            int q = r >> 4;
            int r2 = r & 15;
            int gg = r2 >> 3;
            int tg = (r2 & 7) >> 1;
            int e = r2 & 1;
            int g = gg * 2 + e;
            int h = wnn * 16 + q * 4 + tg;
            int src = g * 128 + h;
            float scale = (g == 2) ? 1.0f : 0.5f;
            const float* bi = (phase == 0) ? ebih0 : (phase == 1) ? ebih1 : (phase == 2) ? dbih0 : dbih1;
            const float* bh = (phase == 0) ? ebhh0 : (phase == 1) ? ebhh1 : (phase == 2) ? dbhh0 : dbhh1;
            g_bias[phase * NG + np] = (bi[src] + bh[src]) * scale;
        }
    }
}

// ---------------- acc init with bias (acc[mi 0..1][ni 0..7][4]) ----------------
__device__ __forceinline__ void init_acc(float (&acc)[2][8][4], const float* bias,
                                         int lane, int wn)
{
#pragma unroll
    for (int ni = 0; ni < 8; ni++) {
        int c0 = wn * 64 + ni * 8 + 2 * (lane & 3);
        float b0 = bias[c0], b1 = bias[c0 + 1];
#pragma unroll
        for (int mi = 0; mi < 2; mi++) {
            acc[mi][ni][0] = b0; acc[mi][ni][1] = b1;
            acc[mi][ni][2] = b0; acc[mi][ni][3] = b1;
        }
    }
}

// ---------------- NSL full slabs: kf-split software-pipelined B LDGs ----------------
// R0 carries kf0 fragments of the NEXT slab (cross-phase: caller keeps it alive).
template <int NSL, int ACOL0>
__device__ __forceinline__ void mma_slabs(
    float (&acc)[2][8][4], uint4 (&R0)[4], int lane, int wn, __half* sH,
    const __half* Wbase, const __half* Wnext)
{
    const uint4* base = (const uint4*)Wbase + wn * 256 + lane;
    const uint4* nbase = (const uint4*)Wnext + wn * 256 + lane;
#pragma unroll
    for (int j = 0; j < NSL; j++) {
        const int acol = ACOL0 + j * 32;

        uint4 R1[4];
#pragma unroll
        for (int c = 0; c < 4; c++) R1[c] = __ldg(base + j * SLABU + (4 + c) * 32);

        {   // MMA kf0 (uses R0, pre-loaded)
            unsigned a[2][4];
#pragma unroll
            for (int mi = 0; mi < 2; mi++) {
                unsigned addr = smem_u32(sH + (mi * 16 + (lane & 15)) * LDA
                                            + acol + (lane >> 4) * 8);
                ldsm4(addr, a[mi][0], a[mi][1], a[mi][2], a[mi][3]);
            }
#pragma unroll
            for (int nq = 0; nq < 4; nq++) {
                const uint4& cA = R0[nq];
#pragma unroll
                for (int mi = 0; mi < 2; mi++) {
                    mma16816(acc[mi][2 * nq],     a[mi], cA.x, cA.y);
                    mma16816(acc[mi][2 * nq + 1], a[mi], cA.z, cA.w);
                }
            }
        }

        const uint4* nxt = (j + 1 < NSL) ? base + (j + 1) * SLABU : nbase;
#pragma unroll
        for (int c = 0; c < 4; c++) R0[c] = __ldg(nxt + c * 32);

        {   // MMA kf1 (uses R1)
            unsigned a[2][4];
#pragma unroll
            for (int mi = 0; mi < 2; mi++) {
                unsigned addr = smem_u32(sH + (mi * 16 + (lane & 15)) * LDA
                                            + acol + 16 + (lane >> 4) * 8);
                ldsm4(addr, a[mi][0], a[mi][1], a[mi][2], a[mi][3]);
            }
#pragma unroll
            for (int nq = 0; nq < 4; nq++) {
                const uint4& cB = R1[nq];
#pragma unroll
                for (int mi = 0; mi < 2; mi++) {
                    mma16816(acc[mi][2 * nq],     a[mi], cB.x, cB.y);
                    mma16816(acc[mi][2 * nq + 1], a[mi], cB.z, cB.w);
                }
            }
        }
    }
}

// ---------------- half slab: consumes R0 (kf0 of the half slab, K 128..143) ----------
// Preloads kf0 of the next phase's first slab into R0.
__device__ __forceinline__ void mma_halfslab(
    float (&acc)[2][8][4], uint4 (&R0)[4], int lane, int wn, __half* sH,
    const __half* Wnext)
{
    const uint4* nbase = (const uint4*)Wnext + wn * 256 + lane;
    uint4 Rn[4];
#pragma unroll
    for (int c = 0; c < 4; c++) Rn[c] = __ldg(nbase + c * 32);

    unsigned a[2][4];
#pragma unroll
    for (int mi = 0; mi < 2; mi++) {
        unsigned addr = smem_u32(sH + (mi * 16 + (lane & 15)) * LDA
                                    + 128 + (lane >> 4) * 8);
        ldsm4(addr, a[mi][0], a[mi][1], a[mi][2], a[mi][3]);
    }
#pragma unroll
    for (int nq = 0; nq < 4; nq++) {
        const uint4& cA = R0[nq];
#pragma unroll
        for (int mi = 0; mi < 2; mi++) {
            mma16816(acc[mi][2 * nq],     a[mi], cA.x, cA.y);
            mma16816(acc[mi][2 * nq + 1], a[mi], cA.z, cA.w);
        }
    }
#pragma unroll
    for (int c = 0; c < 4; c++) R0[c] = Rn[c];
}

// ---------------- shuffle-free epilogue: compute / store ----------------
__device__ __forceinline__ void epi_compute(
    float (&acc)[2][8][4], int lane, int wn, float* sC, unsigned (&hh)[8])
{
    const int t = lane & 3, a = lane >> 2;
    const __half2 h05 = __floats2half2_rn(0.5f, 0.5f);
#pragma unroll
    for (int mi = 0; mi < 2; mi++) {
        int r0 = mi * 16 + a;
#pragma unroll
        for (int q = 0; q < 4; q++) {
            float* dA = acc[mi][2 * q];
            float* dB = acc[mi][2 * q + 1];
            __half2 si = __hfma2(u2h(tanh2u(pack2(dA[0], dA[2]))), h05, h05);
            __half2 sf = __hfma2(u2h(tanh2u(pack2(dA[1], dA[3]))), h05, h05);
            __half2 tg = u2h(tanh2u(pack2(dB[0], dB[2])));
            __half2 so = __hfma2(u2h(tanh2u(pack2(dB[1], dB[3]))), h05, h05);
            int hidx = wn * 16 + q * 4 + t;
            float2 fsi = __half22float2(si);
            float2 fsf = __half22float2(sf);
            float2 ftg = __half22float2(tg);
            float c0 = fsf.x * sC[r0 * LDC + hidx] + fsi.x * ftg.x;
            float c1 = fsf.y * sC[(r0 + 8) * LDC + hidx] + fsi.y * ftg.y;
            sC[r0 * LDC + hidx] = c0;
            sC[(r0 + 8) * LDC + hidx] = c1;
            __half2 hv = __hmul2(u2h(tanh2u(pack2(c0, c1))), so);
            hh[mi * 4 + q] = *reinterpret_cast<unsigned*>(&hv);
        }
    }
}
__device__ __forceinline__ void epi_store(
    const unsigned (&hh)[8], int lane, int wn, __half* sH, int hOff)
{
    const int t = lane & 3, a = lane >> 2;
#pragma unroll
    for (int mi = 0; mi < 2; mi++) {
        int r0 = mi * 16 + a;
#pragma unroll
        for (int q = 0; q < 4; q++) {
            __half2 hv = u2h(hh[mi * 4 + q]);
            int hidx = wn * 16 + q * 4 + t;
            sH[r0 * LDA + hOff + hidx]       = __low2half(hv);
            sH[(r0 + 8) * LDA + hOff + hidx] = __high2half(hv);
        }
    }
}

// ---------------- the fused full-network kernel (2 CTAs/SM) ----------------
__global__ __launch_bounds__(NT, 2)
void lstm_fused(const float* __restrict__ target,
                const float* __restrict__ outW, const float* __restrict__ outb,
                float* __restrict__ dout)
{
    extern __shared__ char smem[];
    __half* sH    = (__half*)(smem + SMO_H);
    float*  sC0   = (float*)(smem + SMO_C0);
    float*  sC1   = (float*)(smem + SMO_C1);
    float*  sBias = (float*)(smem + SMO_BIAS);
    float*  sOW   = (float*)(smem + SMO_OW);
    float*  sOB   = (float*)(smem + SMO_OB);

    int tid  = threadIdx.x;
    int warp = tid >> 5, lane = tid & 31;
    long m0 = (long)blockIdx.x * MT;

    // ---- init ----
    for (int i = tid; i < MT * LDA; i += NT) sH[i] = __float2half(0.0f);
    for (int i = tid; i < MT * LDC; i += NT) { sC0[i] = 0.0f; sC1[i] = 0.0f; }
    for (int i = tid; i < 4 * NG; i += NT) sBias[i] = g_bias[i];
    if (tid < 256) sOW[tid] = outW[tid];
    if (tid < 2) sOB[tid] = outb[tid];
    for (int i = tid; i < MT * 7; i += NT) {    // stage x(0)
        int m = i / 7, k = i - m * 7;
        sH[m * LDA + 128 + k] = __float2half(target[(m0 + m) * 140 + k]);
    }
    __syncthreads();

    float acc[2][8][4];
    unsigned hh[8];
    uint4 R0[4];
    {   // prologue: preload phase-0 slab-0 kf0 fragments
        const uint4* p0 = (const uint4*)g_S + warp * 256 + lane;
#pragma unroll
        for (int c = 0; c < 4; c++) R0[c] = __ldg(p0 + c * 32);
    }

    // ---- encoder: 20 steps ----
    for (int t = 0; t < 20; t++) {
        // P1: layer0 (4 full slabs @0..127 + half slab @128..143) + epi0 compute
        init_acc(acc, sBias, lane, warp);
        mma_slabs<4, 0>(acc, R0, lane, warp, sH, g_S, g_S + 4 * SLABH);
        mma_halfslab(acc, R0, lane, warp, sH, g_S + 5 * SLABH);
        epi_compute(acc, lane, warp, sC0, hh);
        __syncthreads();
        // P2: epi0 store (h0 @0..127) + layer1 h1-slabs (read 160..287)
        epi_store(hh, lane, warp, sH, 0);
        init_acc(acc, sBias + NG, lane, warp);
        mma_slabs<4, 160>(acc, R0, lane, warp, sH, g_S + 5 * SLABH, g_S + 9 * SLABH);
        __syncthreads();
        // P3: layer1 h0-slabs (read 0..127) + epi1 (write 160..287) + stage-x
        mma_slabs<4, 0>(acc, R0, lane, warp, sH, g_S + 9 * SLABH,
                        (t < 19) ? g_S : g_S + 13 * SLABH);
        epi_compute(acc, lane, warp, sC1, hh);
        epi_store(hh, lane, warp, sH, 160);
        if (t < 19) {
            for (int i = tid; i < MT * 7; i += NT) {
                int m = i / 7, k = i - m * 7;
                sH[m * LDA + 128 + k] = __float2half(target[(m0 + m) * 140 + (t + 1) * 7 + k]);
            }
        }
        __syncthreads();
    }

    // zero pred input for first decoder step (cols 130..143 hit zero weights)
    for (int i = tid; i < MT * 2; i += NT) {
        int m = i >> 1, k = i & 1;
        sH[m * LDA + 128 + k] = __float2half(0.0f);
    }
    __syncthreads();

    // ---- decoder: 25 steps (R15 structure, half-slab only) ----
    for (int t = 0; t < 25; t++) {
        init_acc(acc, sBias + 2 * NG, lane, warp);
        mma_slabs<4, 0>(acc, R0, lane, warp, sH, g_S + 13 * SLABH, g_S + 17 * SLABH);
        mma_halfslab(acc, R0, lane, warp, sH, g_S + 18 * SLABH);
        epi_compute(acc, lane, warp, sC0, hh);
        __syncthreads();
        epi_store(hh, lane, warp, sH, 0);
        init_acc(acc, sBias + 3 * NG, lane, warp);
        mma_slabs<4, 160>(acc, R0, lane, warp, sH, g_S + 18 * SLABH, g_S + 22 * SLABH);
        __syncthreads();
        mma_slabs<4, 0>(acc, R0, lane, warp, sH, g_S + 22 * SLABH, g_S + 13 * SLABH);
        epi_compute(acc, lane, warp, sC1, hh);
        epi_store(hh, lane, warp, sH, 160);
        __syncthreads();   // h1 complete before projection

        // projection: pred = h1 @ outW^T + outb (8 warps x 4 rows)
#pragma unroll
        for (int r4 = 0; r4 < 4; r4++) {
            int mloc = warp * 4 + r4;
            float a0 = 0.0f, a1 = 0.0f;
#pragma unroll
            for (int j = 0; j < 4; j++) {
                int k = lane + 32 * j;
                float hv = __half2float(sH[mloc * LDA + 160 + k]);
                a0 += hv * sOW[k];
                a1 += hv * sOW[128 + k];
            }
#pragma unroll
            for (int off = 16; off > 0; off >>= 1) {
                a0 += __shfl_down_sync(0xffffffffu, a0, off);
                a1 += __shfl_down_sync(0xffffffffu, a1, off);
            }
            if (lane == 0) {
                a0 += sOB[0];
                a1 += sOB[1];
                long m = m0 + mloc;
                dout[m * 50 + t * 2 + 0] = a0;
                dout[m * 50 + t * 2 + 1] = a1;
                sH[mloc * LDA + 128] = __float2half(a0);
                sH[mloc * LDA + 129] = __float2half(a1);
            }
        }
        __syncthreads();   // pred visible to next layer0
    }
}

// ---------------- host ----------------
extern "C" void kernel_launch(void* const* d_in, const int* in_sizes, int n_in,
                              void* d_out, int out_size)
{
    const float* target = (const float*)d_in[0];
    const float* eWih0 = (const float*)d_in[4];
    const float* eWhh0 = (const float*)d_in[5];
    const float* ebih0 = (const float*)d_in[6];
    const float* ebhh0 = (const float*)d_in[7];
    const float* eWih1 = (const float*)d_in[8];
    const float* eWhh1 = (const float*)d_in[9];
    const float* ebih1 = (const float*)d_in[10];
    const float* ebhh1 = (const float*)d_in[11];
    const float* dWih0 = (const float*)d_in[12];
    const float* dWhh0 = (const float*)d_in[13];
    const float* dbih0 = (const float*)d_in[14];
    const float* dbhh0 = (const float*)d_in[15];
    const float* dWih1 = (const float*)d_in[16];
    const float* dWhh1 = (const float*)d_in[17];
    const float* dbih1 = (const float*)d_in[18];
    const float* dbhh1 = (const float*)d_in[19];
    const float* outW  = (const float*)d_in[20];
    const float* outb  = (const float*)d_in[21];
    float* out = (float*)d_out;

    cudaFuncSetAttribute(lstm_fused, cudaFuncAttributeMaxDynamicSharedMemorySize, SMEM_TOTAL);

    build_weights<<<26, 256>>>(eWih0, eWhh0, ebih0, ebhh0,
                               eWih1, eWhh1, ebih1, ebhh1,
                               dWih0, dWhh0, dbih0, dbhh0,
                               dWih1, dWhh1, dbih1, dbhh1);

    lstm_fused<<<BATCH / MT, NT, SMEM_TOTAL>>>(target, outW, outb, out);
}